// round 8
// baseline (speedup 1.0000x reference)
#include <cuda_runtime.h>
#include <math.h>

// Problem constants
#define BB 131072      // batch rows
#define DD 64          // feature dim
#define dd 32          // half dim
#define HH 512         // hidden width
#define NLAYER 3       // hidden layers
#define NBLK 8         // coupling blocks
#define EPS 1e-5f

// ---------------- scratch (static device globals; no allocation) -------------
__device__ float g_h1[(size_t)BB * HH];   // 256 MiB activation ping
__device__ float g_h2[(size_t)BB * HH];   // 256 MiB activation pong
__device__ float g_yb[(size_t)BB * DD];   // BN-applied block input
__device__ float g_zb[(size_t)BB * DD];   // pre-BN block output z
__device__ float g_sb[(size_t)BB * dd];   // s_out
__device__ float g_tb[(size_t)BB * dd];   // t_out
__device__ float g_logdet[BB];
__device__ double g_csum[DD];
__device__ double g_csumsq[DD];
__device__ float g_scale[DD];             // exp(lg)*invstd
__device__ float g_shift[DD];             // beta - mean*scale
__device__ float g_scalar;                // scalar log-det accumulator

// ---------------- init -------------------------------------------------------
__global__ void k_init() {
    int idx = blockIdx.x * blockDim.x + threadIdx.x;
    if (idx < BB) g_logdet[idx] = 0.0f;
    if (idx < DD) { g_csum[idx] = 0.0; g_csumsq[idx] = 0.0; }
    if (idx == 0) g_scalar = 0.0f;
}

// ---------------- GEMM: C = act(A @ W + bias) --------------------------------
// A: M x K (row stride lda), W: K x N (row stride ldb), C: M x N (row stride ldc)
// M is always BB (multiple of 128). N,K multiples of 32, BK=8 divides K.
#define BM 128
#define BN 128
#define BK 8

__global__ __launch_bounds__(256) void k_gemm(
    const float* __restrict__ A, int lda,
    const float* __restrict__ W, int ldb,
    const float* __restrict__ bias,
    float* __restrict__ C, int ldc,
    int N, int K, int act)
{
    __shared__ float As[BK][BM];
    __shared__ float Bs[BK][BN];

    const int tid = threadIdx.x;
    const int bm = blockIdx.y * BM;
    const int bn = blockIdx.x * BN;

    // A tile load mapping: 128 rows x 8 cols -> 256 float4
    const int arow = tid >> 1;
    const int acol = (tid & 1) << 2;
    // B tile load mapping: 8 rows x 128 cols -> 256 float4
    const int brow = tid >> 5;
    const int bcol = (tid & 31) << 2;

    const float* Ap = A + (size_t)(bm + arow) * lda + acol;
    const float* Bp = W + (size_t)brow * ldb + bn + bcol;
    const bool bok = (bn + bcol) < N;   // N is a multiple of 32, bcol multiple of 4

    float4 a0 = *(const float4*)Ap;
    float4 b0 = bok ? *(const float4*)Bp : make_float4(0.f, 0.f, 0.f, 0.f);

    float acc[8][8];
#pragma unroll
    for (int i = 0; i < 8; ++i)
#pragma unroll
        for (int j = 0; j < 8; ++j) acc[i][j] = 0.0f;

    const int ty = tid >> 4;
    const int tx = tid & 15;
    const int nT = K / BK;

    for (int t = 0; t < nT; ++t) {
        As[acol + 0][arow] = a0.x;
        As[acol + 1][arow] = a0.y;
        As[acol + 2][arow] = a0.z;
        As[acol + 3][arow] = a0.w;
        *(float4*)&Bs[brow][bcol] = b0;
        __syncthreads();

        if (t + 1 < nT) {
            a0 = *(const float4*)(Ap + (size_t)(t + 1) * BK);
            b0 = bok ? *(const float4*)(Bp + (size_t)(t + 1) * BK * ldb)
                     : make_float4(0.f, 0.f, 0.f, 0.f);
        }

#pragma unroll
        for (int kk = 0; kk < BK; ++kk) {
            float ra[8], rb[8];
            *(float4*)&ra[0] = *(const float4*)&As[kk][ty * 8];
            *(float4*)&ra[4] = *(const float4*)&As[kk][ty * 8 + 4];
            *(float4*)&rb[0] = *(const float4*)&Bs[kk][tx * 8];
            *(float4*)&rb[4] = *(const float4*)&Bs[kk][tx * 8 + 4];
#pragma unroll
            for (int i = 0; i < 8; ++i)
#pragma unroll
                for (int j = 0; j < 8; ++j)
                    acc[i][j] = fmaf(ra[i], rb[j], acc[i][j]);
        }
        __syncthreads();
    }

    // epilogue: bias + activation
#pragma unroll
    for (int i = 0; i < 8; ++i) {
        const size_t row = (size_t)(bm + ty * 8 + i);
#pragma unroll
        for (int j = 0; j < 8; ++j) {
            const int col = bn + tx * 8 + j;
            if (col < N) {
                float v = acc[i][j] + bias[col];
                if (act == 1)      v = tanhf(v);
                else if (act == 2) v = fmaxf(v, 0.0f);
                C[row * ldc + col] = v;
            }
        }
    }
}

// ---------------- BN apply: g_yb = g_zb * scale + shift -----------------------
__global__ void k_bnapply() {
    int idx = blockIdx.x * blockDim.x + threadIdx.x;
    if (idx < BB * DD) {
        int c = idx & (DD - 1);
        g_yb[idx] = g_zb[idx] * g_scale[c] + g_shift[c];
    }
}

// ---------------- coupling: zc = yc*exp(s)+t; copy ys; logdet += rowsum(s) ----
// One warp per row; lane j handles column j of the half.
__global__ void k_couple(const float* __restrict__ ysrc, int sOff) {
    int gt = blockIdx.x * blockDim.x + threadIdx.x;
    int row = gt >> 5;
    int j = gt & 31;
    if (row >= BB) return;
    int cOff = dd - sOff;

    float sv = g_sb[(size_t)row * dd + j];
    float tv = g_tb[(size_t)row * dd + j];
    float ys = ysrc[(size_t)row * DD + sOff + j];
    float yc = ysrc[(size_t)row * DD + cOff + j];
    float zc = yc * expf(sv) + tv;

    g_zb[(size_t)row * DD + sOff + j] = ys;
    g_zb[(size_t)row * DD + cOff + j] = zc;

    float sum = sv;
#pragma unroll
    for (int o = 16; o > 0; o >>= 1) sum += __shfl_xor_sync(0xffffffffu, sum, o);
    if (j == 0) g_logdet[row] += sum;
}

// ---------------- column stats over g_zb --------------------------------------
// grid = 128 blocks, block = (64, 8); each block handles 1024 rows.
__global__ void k_colstats() {
    int c = threadIdx.x;
    int r = threadIdx.y;
    int start = blockIdx.x * 1024;
    float s = 0.0f, q = 0.0f;
    for (int i = start + r; i < start + 1024; i += 8) {
        float v = g_zb[(size_t)i * DD + c];
        s += v;
        q += v * v;
    }
    __shared__ float shs[8][64];
    __shared__ float shq[8][64];
    shs[r][c] = s;
    shq[r][c] = q;
    __syncthreads();
    if (r == 0) {
        double S = 0.0, Q = 0.0;
#pragma unroll
        for (int k = 0; k < 8; ++k) { S += (double)shs[k][c]; Q += (double)shq[k][c]; }
        atomicAdd(&g_csum[c], S);
        atomicAdd(&g_csumsq[c], Q);
    }
}

// ---------------- finalize stats: scale/shift + scalar logdet; reset sums -----
__global__ void k_finalize(const float* __restrict__ lg, const float* __restrict__ bt, int b) {
    int c = threadIdx.x;  // 64 threads
    double mean = g_csum[c] / (double)BB;
    double var = (g_csumsq[c] - (double)BB * mean * mean) / (double)(BB - 1);
    double vpe = var + (double)EPS;
    float invstd = (float)(1.0 / sqrt(vpe));
    float lgc = lg[b * DD + c];
    float sc = expf(lgc) * invstd;
    g_scale[c] = sc;
    g_shift[c] = bt[b * DD + c] - (float)mean * sc;
    float term = lgc - 0.5f * (float)log(vpe);
    g_csum[c] = 0.0;
    g_csumsq[c] = 0.0;

    __shared__ float red[64];
    red[c] = term;
    __syncthreads();
    for (int o = 32; o > 0; o >>= 1) {
        if (c < o) red[c] += red[c + o];
        __syncthreads();
    }
    if (c == 0) g_scalar += red[0];
}

// ---------------- output: y = BN(z) then logdet ------------------------------
__global__ void k_output(float* __restrict__ out) {
    int idx = blockIdx.x * blockDim.x + threadIdx.x;
    if (idx < BB * DD) {
        int c = idx & (DD - 1);
        out[idx] = g_zb[idx] * g_scale[c] + g_shift[c];
    } else if (idx < BB * DD + BB) {
        int i = idx - BB * DD;
        out[(size_t)BB * DD + i] = g_logdet[i] + g_scalar;
    }
}

// ---------------- launcher ----------------------------------------------------
extern "C" void kernel_launch(void* const* d_in, const int* in_sizes, int n_in,
                              void* d_out, int out_size) {
    (void)in_sizes; (void)n_in; (void)out_size;
    const float* y   = (const float*)d_in[0];
    const float* sW0 = (const float*)d_in[1];
    const float* sb0 = (const float*)d_in[2];
    const float* sWh = (const float*)d_in[3];
    const float* sbh = (const float*)d_in[4];
    const float* sWo = (const float*)d_in[5];
    const float* sbo = (const float*)d_in[6];
    const float* tW0 = (const float*)d_in[7];
    const float* tb0 = (const float*)d_in[8];
    const float* tWh = (const float*)d_in[9];
    const float* tbh = (const float*)d_in[10];
    const float* tWo = (const float*)d_in[11];
    const float* tbo = (const float*)d_in[12];
    const float* lg  = (const float*)d_in[13];
    const float* bt  = (const float*)d_in[14];
    float* out = (float*)d_out;

    float *h1, *h2, *yb, *sb, *tb;
    cudaGetSymbolAddress((void**)&h1, g_h1);
    cudaGetSymbolAddress((void**)&h2, g_h2);
    cudaGetSymbolAddress((void**)&yb, g_yb);
    cudaGetSymbolAddress((void**)&sb, g_sb);
    cudaGetSymbolAddress((void**)&tb, g_tb);

    k_init<<<(BB + 255) / 256, 256>>>();

    dim3 gridH(HH / BN, BB / BM);  // (4, 1024) hidden / first layers (N=512)
    dim3 gridO(1, BB / BM);        // output layers (N=32)

    for (int b = 0; b < NBLK; ++b) {
        const float* ysrc = (b == 0) ? y : yb;
        if (b > 0) k_bnapply<<<(BB * DD + 255) / 256, 256>>>();
        const int sOff = (b & 1) ? dd : 0;

        // ---- s MLP (tanh) ----
        k_gemm<<<gridH, 256>>>(ysrc + sOff, DD,
                               sW0 + (size_t)b * dd * HH, HH, sb0 + (size_t)b * HH,
                               h1, HH, HH, dd, 1);
        float* cur = h1; float* nxt = h2;
        for (int l = 0; l < NLAYER; ++l) {
            k_gemm<<<gridH, 256>>>(cur, HH,
                                   sWh + ((size_t)(b * NLAYER + l)) * HH * HH, HH,
                                   sbh + (size_t)(b * NLAYER + l) * HH,
                                   nxt, HH, HH, HH, 1);
            float* tmp = cur; cur = nxt; nxt = tmp;
        }
        k_gemm<<<gridO, 256>>>(cur, HH,
                               sWo + (size_t)b * HH * dd, dd, sbo + (size_t)b * dd,
                               sb, dd, dd, HH, 0);

        // ---- t MLP (relu) ----
        k_gemm<<<gridH, 256>>>(ysrc + sOff, DD,
                               tW0 + (size_t)b * dd * HH, HH, tb0 + (size_t)b * HH,
                               h1, HH, HH, dd, 2);
        cur = h1; nxt = h2;
        for (int l = 0; l < NLAYER; ++l) {
            k_gemm<<<gridH, 256>>>(cur, HH,
                                   tWh + ((size_t)(b * NLAYER + l)) * HH * HH, HH,
                                   tbh + (size_t)(b * NLAYER + l) * HH,
                                   nxt, HH, HH, HH, 2);
            float* tmp = cur; cur = nxt; nxt = tmp;
        }
        k_gemm<<<gridO, 256>>>(cur, HH,
                               tWo + (size_t)b * HH * dd, dd, tbo + (size_t)b * dd,
                               tb, dd, dd, HH, 0);

        // ---- coupling + stats ----
        k_couple<<<(BB * 32 + 255) / 256, 256>>>(ysrc, sOff);
        k_colstats<<<128, dim3(64, 8)>>>();
        k_finalize<<<1, 64>>>(lg, bt, b);
    }

    k_output<<<(BB * DD + BB + 255) / 256, 256>>>(out);
}

// round 10
// speedup vs baseline: 2.8125x; 2.8125x over previous
#include <cuda_runtime.h>
#include <cuda_bf16.h>
#include <cstdint>
#include <math.h>

// Problem constants
#define BB 131072
#define DD 64
#define dd 32
#define HH 512
#define NLAYER 3
#define NBLK 8
#define EPS 1e-5f

// ---------------------------------------------------------------------------
// asm helpers (sm_80-era instructions only: valid at compute_103 target)
// ---------------------------------------------------------------------------
__device__ __forceinline__ uint32_t smem_u32(const void* p) {
    uint32_t a;
    asm("{ .reg .u64 t; cvta.to.shared.u64 t, %1; cvt.u32.u64 %0, t; }" : "=r"(a) : "l"(p));
    return a;
}
#define CP16(S, G) \
    asm volatile("cp.async.cg.shared.global [%0], [%1], 16;" :: "r"(S), "l"(G))
#define CP_COMMIT() asm volatile("cp.async.commit_group;" ::: "memory")
#define CP_WAIT1()  asm volatile("cp.async.wait_group 1;" ::: "memory")

#define LDSM4(R, ADDR) \
    asm volatile("ldmatrix.sync.aligned.m8n8.x4.shared.b16 {%0,%1,%2,%3}, [%4];" \
        : "=r"((R)[0]), "=r"((R)[1]), "=r"((R)[2]), "=r"((R)[3]) : "r"(ADDR))

#define MMA_BF16(D, A, B0, B1) \
    asm volatile("mma.sync.aligned.m16n8k16.row.col.f32.bf16.bf16.f32 " \
        "{%0,%1,%2,%3}, {%4,%5,%6,%7}, {%8,%9}, {%0,%1,%2,%3};" \
        : "+f"((D)[0]), "+f"((D)[1]), "+f"((D)[2]), "+f"((D)[3]) \
        : "r"((A)[0]), "r"((A)[1]), "r"((A)[2]), "r"((A)[3]), "r"(B0), "r"(B1))

// ---------------------------------------------------------------------------
// scratch (static device globals; no allocation)
// ---------------------------------------------------------------------------
__device__ __nv_bfloat16 g_h1h[(size_t)BB * HH];
__device__ __nv_bfloat16 g_h1l[(size_t)BB * HH];
__device__ __nv_bfloat16 g_h2h[(size_t)BB * HH];
__device__ __nv_bfloat16 g_h2l[(size_t)BB * HH];
__device__ __nv_bfloat16 g_y0h[(size_t)BB * dd];
__device__ __nv_bfloat16 g_y0l[(size_t)BB * dd];
__device__ float g_yb[(size_t)BB * DD];
__device__ float g_zb[(size_t)BB * DD];
__device__ float g_sb[(size_t)BB * dd];
__device__ float g_tb[(size_t)BB * dd];
__device__ float g_logdet[BB];
__device__ double g_csum[DD];
__device__ double g_csumsq[DD];
__device__ float g_scale[DD];
__device__ float g_shift[DD];
__device__ float g_scalar;

// weight blobs: [N][K] bf16, hi and lo splits
// hidden: 48 x (512*512) ; layer0: 16 x (512*32) ; out: 16 x (32*512)
#define HBLK_E   262144UL
#define HIDTOT_E (48UL * HBLK_E)
#define L0BLK_E  16384UL
#define L0TOT_E  (16UL * L0BLK_E)
#define OBLK_E   16384UL
#define WTOT_E   (HIDTOT_E + L0TOT_E + 16UL * OBLK_E)
__device__ __nv_bfloat16 g_whi[WTOT_E];
__device__ __nv_bfloat16 g_wlo[WTOT_E];

// ---------------------------------------------------------------------------
// helpers
// ---------------------------------------------------------------------------
__device__ __forceinline__ void split1(float v, __nv_bfloat16& h, __nv_bfloat16& l) {
    h = __float2bfloat16(v);
    l = __float2bfloat16(v - __bfloat162float(h));
}
__device__ __forceinline__ uint32_t pack2(__nv_bfloat16 a, __nv_bfloat16 b) {
    return (uint32_t)__bfloat16_as_ushort(a) | ((uint32_t)__bfloat16_as_ushort(b) << 16);
}
__device__ __forceinline__ float fast_tanh(float x) {
    float e = __expf(2.0f * x);
    return 1.0f - __fdividef(2.0f, e + 1.0f);
}

// ---------------------------------------------------------------------------
// weight prep: W[K][N] fp32 -> blob[n*K + k] bf16 hi/lo
// ---------------------------------------------------------------------------
__global__ void k_prep_h(const float* __restrict__ sWh, const float* __restrict__ tWh) {
    int z = blockIdx.z, b = z / 6, r = z % 6;
    const float* W = (r < 3) ? sWh + (size_t)(b * 3 + r) * HH * HH
                             : tWh + (size_t)(b * 3 + (r - 3)) * HH * HH;
    int idx = blockIdx.x * 256 + threadIdx.x;            // 0..262143
    int k = idx & 511, n = idx >> 9;
    float v = W[(size_t)k * HH + n];
    __nv_bfloat16 h, l; split1(v, h, l);
    size_t o = (size_t)z * HBLK_E + (size_t)n * HH + k;
    g_whi[o] = h; g_wlo[o] = l;
}
__global__ void k_prep_l0(const float* __restrict__ sW0, const float* __restrict__ tW0) {
    int z = blockIdx.z, b = z >> 1, m = z & 1;
    const float* W = (m ? tW0 : sW0) + (size_t)b * dd * HH;   // [32][512]
    int idx = blockIdx.x * 256 + threadIdx.x;                 // 0..16383
    int k = idx & 31, n = idx >> 5;
    float v = W[(size_t)k * HH + n];
    __nv_bfloat16 h, l; split1(v, h, l);
    size_t o = HIDTOT_E + (size_t)z * L0BLK_E + (size_t)n * dd + k;
    g_whi[o] = h; g_wlo[o] = l;
}
__global__ void k_prep_out(const float* __restrict__ sWo, const float* __restrict__ tWo) {
    int z = blockIdx.z, b = z >> 1, m = z & 1;
    const float* W = (m ? tWo : sWo) + (size_t)b * HH * dd;   // [512][32]
    int idx = blockIdx.x * 256 + threadIdx.x;                 // 0..16383
    int k = idx & 511, n = idx >> 9;
    float v = W[(size_t)k * dd + n];
    __nv_bfloat16 h, l; split1(v, h, l);
    size_t o = HIDTOT_E + L0TOT_E + (size_t)z * OBLK_E + (size_t)n * HH + k;
    g_whi[o] = h; g_wlo[o] = l;
}
// y first-block s-half -> y0 hi/lo
__global__ void k_prep_y0(const float* __restrict__ y) {
    int idx = blockIdx.x * 256 + threadIdx.x;   // BB*32
    int r = idx >> 5, c = idx & 31;
    float v = y[(size_t)r * DD + c];            // sOff = 0 for block 0
    __nv_bfloat16 h, l; split1(v, h, l);
    g_y0h[idx] = h; g_y0l[idx] = l;
}

// ---------------------------------------------------------------------------
// HMMA GEMM: C[M,N] = act(A[M,K] @ W[K,N] + bias), bf16 hi/lo x3
// grid = (N/BN, M/128), block = 256. A = (Ahi, Alo) bf16 [M][K].
// B blobs [N][K] bf16. Hidden: writes Chi/Clo. ACT==0: writes fp32 Cf.
// ---------------------------------------------------------------------------
template <int BN, int NK, int ACT>
__global__ void __launch_bounds__(256, 1) k_mma(
    const __nv_bfloat16* __restrict__ Ahi, const __nv_bfloat16* __restrict__ Alo,
    const __nv_bfloat16* __restrict__ Bhi, const __nv_bfloat16* __restrict__ Blo,
    const float* __restrict__ bias,
    __nv_bfloat16* __restrict__ Chi, __nv_bfloat16* __restrict__ Clo,
    float* __restrict__ Cf, int ldc)
{
    constexpr int K   = NK * 32;
    constexpr int WGM = (BN == 128) ? 2 : 8;
    constexpr int MT  = 128 / (16 * WGM);
    constexpr int NT  = 4;                    // both variants: 4 n-tiles/warp
    constexpr uint32_t AST = 128 * 80;        // one A half (hi or lo) per stage
    constexpr uint32_t BST = BN * 80;
    constexpr uint32_t SS  = 2 * AST + 2 * BST;
    constexpr int T_TOT = 1024 + BN * 8;      // cp.async 16B tasks per stage

    extern __shared__ unsigned char smraw[];
    const uint32_t sb = smem_u32(smraw);
    const int tid = threadIdx.x;
    const int wid = tid >> 5;
    const int L = tid & 31;
    const size_t bm = (size_t)blockIdx.y * 128;
    const int bn = blockIdx.x * BN;
    const int wm = (BN == 128) ? (wid >> 2) * 64 : wid * 16;
    const int wn = (BN == 128) ? (wid & 3) * 32 : 0;

    float acc[MT][NT][4];
#pragma unroll
    for (int i = 0; i < MT; ++i)
#pragma unroll
        for (int j = 0; j < NT; ++j)
#pragma unroll
            for (int q = 0; q < 4; ++q) acc[i][j][q] = 0.0f;

    // ldmatrix lane address bases (80B-padded rows -> conflict-free)
    const uint32_t a_off = (uint32_t)(wm + (L & 15)) * 80u + (uint32_t)((L >> 4) << 4);
    const uint32_t b_off = (uint32_t)(wn + (L & 7)) * 80u + (uint32_t)((L >> 3) << 4);

    auto load_stage = [&](int st, int kc) {
        const uint32_t s0 = sb + (uint32_t)st * SS;
        const size_t akb = (size_t)kc * 32;
#pragma unroll
        for (int q = tid; q < T_TOT; q += 256) {
            if (q < 512) {
                int r = q >> 2, c = q & 3;
                CP16(s0 + (uint32_t)r * 80u + (uint32_t)c * 16u,
                     Ahi + (bm + r) * K + akb + c * 8);
            } else if (q < 1024) {
                int p = q - 512; int r = p >> 2, c = p & 3;
                CP16(s0 + AST + (uint32_t)r * 80u + (uint32_t)c * 16u,
                     Alo + (bm + r) * K + akb + c * 8);
            } else if (q < 1024 + BN * 4) {
                int p = q - 1024; int r = p >> 2, c = p & 3;
                CP16(s0 + 2 * AST + (uint32_t)r * 80u + (uint32_t)c * 16u,
                     Bhi + (size_t)(bn + r) * K + akb + c * 8);
            } else {
                int p = q - 1024 - BN * 4; int r = p >> 2, c = p & 3;
                CP16(s0 + 2 * AST + BST + (uint32_t)r * 80u + (uint32_t)c * 16u,
                     Blo + (size_t)(bn + r) * K + akb + c * 8);
            }
        }
    };

    // prologue: 2 stages in flight
    load_stage(0, 0);
    CP_COMMIT();
    if (NK > 1) load_stage(1, 1);
    CP_COMMIT();

    for (int kc = 0; kc < NK; ++kc) {
        CP_WAIT1();
        __syncthreads();
        const uint32_t s0 = sb + (uint32_t)(kc % 3) * SS;

        uint32_t Bh[NT][4], Bl[NT][4];
#pragma unroll
        for (int j = 0; j < NT; ++j) LDSM4(Bh[j], s0 + 2 * AST + b_off + j * 640u);
#pragma unroll
        for (int j = 0; j < NT; ++j) LDSM4(Bl[j], s0 + 2 * AST + BST + b_off + j * 640u);

#pragma unroll
        for (int ks = 0; ks < 2; ++ks) {
            uint32_t Ah[MT][4], Al[MT][4];
#pragma unroll
            for (int i = 0; i < MT; ++i) LDSM4(Ah[i], s0 + a_off + i * 1280u + ks * 32u);
#pragma unroll
            for (int i = 0; i < MT; ++i) LDSM4(Al[i], s0 + AST + a_off + i * 1280u + ks * 32u);
#pragma unroll
            for (int i = 0; i < MT; ++i)
#pragma unroll
                for (int j = 0; j < NT; ++j) {
                    MMA_BF16(acc[i][j], Ah[i], Bh[j][2 * ks], Bh[j][2 * ks + 1]);
                    MMA_BF16(acc[i][j], Al[i], Bh[j][2 * ks], Bh[j][2 * ks + 1]);
                    MMA_BF16(acc[i][j], Ah[i], Bl[j][2 * ks], Bl[j][2 * ks + 1]);
                }
        }

        if (kc + 2 < NK) load_stage((kc + 2) % 3, kc + 2);
        CP_COMMIT();
    }

    // epilogue
#pragma unroll
    for (int i = 0; i < MT; ++i) {
        const size_t r0 = bm + wm + i * 16 + (L >> 2);
        const size_t r1 = r0 + 8;
#pragma unroll
        for (int j = 0; j < NT; ++j) {
            const int n = bn + wn + j * 8 + ((L & 3) << 1);
            const float2 bs = *(const float2*)(bias + n);
            float v0 = acc[i][j][0] + bs.x;
            float v1 = acc[i][j][1] + bs.y;
            float v2 = acc[i][j][2] + bs.x;
            float v3 = acc[i][j][3] + bs.y;
            if (ACT == 1) {
                v0 = fast_tanh(v0); v1 = fast_tanh(v1);
                v2 = fast_tanh(v2); v3 = fast_tanh(v3);
            } else if (ACT == 2) {
                v0 = fmaxf(v0, 0.f); v1 = fmaxf(v1, 0.f);
                v2 = fmaxf(v2, 0.f); v3 = fmaxf(v3, 0.f);
            }
            if (ACT == 0) {
                *(float2*)(Cf + r0 * ldc + n) = make_float2(v0, v1);
                *(float2*)(Cf + r1 * ldc + n) = make_float2(v2, v3);
            } else {
                __nv_bfloat16 h0, l0, h1, l1, h2, l2, h3, l3;
                split1(v0, h0, l0); split1(v1, h1, l1);
                split1(v2, h2, l2); split1(v3, h3, l3);
                *(uint32_t*)(Chi + r0 * ldc + n) = pack2(h0, h1);
                *(uint32_t*)(Clo + r0 * ldc + n) = pack2(l0, l1);
                *(uint32_t*)(Chi + r1 * ldc + n) = pack2(h2, h3);
                *(uint32_t*)(Clo + r1 * ldc + n) = pack2(l2, l3);
            }
        }
    }
}

// ---------------------------------------------------------------------------
// small kernels
// ---------------------------------------------------------------------------
__global__ void k_init() {
    int idx = blockIdx.x * blockDim.x + threadIdx.x;
    if (idx < BB) g_logdet[idx] = 0.0f;
    if (idx < DD) { g_csum[idx] = 0.0; g_csumsq[idx] = 0.0; }
    if (idx == 0) g_scalar = 0.0f;
}
// BN apply; also emit next layer-0 input (s-half) as bf16 hi/lo
__global__ void k_bnapply(int sOff) {
    int idx = blockIdx.x * blockDim.x + threadIdx.x;
    if (idx < BB * DD) {
        int c = idx & (DD - 1);
        int r = idx >> 6;
        float v = g_zb[idx] * g_scale[c] + g_shift[c];
        g_yb[idx] = v;
        int cc = c - sOff;
        if (cc >= 0 && cc < dd) {
            __nv_bfloat16 h, l; split1(v, h, l);
            size_t o = (size_t)r * dd + cc;
            g_y0h[o] = h; g_y0l[o] = l;
        }
    }
}
__global__ void k_couple(const float* __restrict__ ysrc, int sOff) {
    int gt = blockIdx.x * blockDim.x + threadIdx.x;
    int row = gt >> 5;
    int j = gt & 31;
    if (row >= BB) return;
    int cOff = dd - sOff;
    float sv = g_sb[(size_t)row * dd + j];
    float tv = g_tb[(size_t)row * dd + j];
    float ys = ysrc[(size_t)row * DD + sOff + j];
    float yc = ysrc[(size_t)row * DD + cOff + j];
    float zc = yc * expf(sv) + tv;
    g_zb[(size_t)row * DD + sOff + j] = ys;
    g_zb[(size_t)row * DD + cOff + j] = zc;
    float sum = sv;
#pragma unroll
    for (int o = 16; o > 0; o >>= 1) sum += __shfl_xor_sync(0xffffffffu, sum, o);
    if (j == 0) g_logdet[row] += sum;
}
__global__ void k_colstats() {
    int c = threadIdx.x;
    int r = threadIdx.y;
    int start = blockIdx.x * 1024;
    float s = 0.0f, q = 0.0f;
    for (int i = start + r; i < start + 1024; i += 8) {
        float v = g_zb[(size_t)i * DD + c];
        s += v; q += v * v;
    }
    __shared__ float shs[8][64];
    __shared__ float shq[8][64];
    shs[r][c] = s; shq[r][c] = q;
    __syncthreads();
    if (r == 0) {
        double S = 0.0, Q = 0.0;
#pragma unroll
        for (int k = 0; k < 8; ++k) { S += (double)shs[k][c]; Q += (double)shq[k][c]; }
        atomicAdd(&g_csum[c], S);
        atomicAdd(&g_csumsq[c], Q);
    }
}
__global__ void k_finalize(const float* __restrict__ lg, const float* __restrict__ bt, int b) {
    int c = threadIdx.x;
    double mean = g_csum[c] / (double)BB;
    double var = (g_csumsq[c] - (double)BB * mean * mean) / (double)(BB - 1);
    double vpe = var + (double)EPS;
    float invstd = (float)(1.0 / sqrt(vpe));
    float lgc = lg[b * DD + c];
    float sc = expf(lgc) * invstd;
    g_scale[c] = sc;
    g_shift[c] = bt[b * DD + c] - (float)mean * sc;
    float term = lgc - 0.5f * (float)log(vpe);
    g_csum[c] = 0.0;
    g_csumsq[c] = 0.0;
    __shared__ float red[64];
    red[c] = term;
    __syncthreads();
    for (int o = 32; o > 0; o >>= 1) {
        if (c < o) red[c] += red[c + o];
        __syncthreads();
    }
    if (c == 0) g_scalar += red[0];
}
__global__ void k_output(float* __restrict__ out) {
    int idx = blockIdx.x * blockDim.x + threadIdx.x;
    if (idx < BB * DD) {
        int c = idx & (DD - 1);
        out[idx] = g_zb[idx] * g_scale[c] + g_shift[c];
    } else if (idx < BB * DD + BB) {
        int i = idx - BB * DD;
        out[(size_t)BB * DD + i] = g_logdet[i] + g_scalar;
    }
}

// ---------------------------------------------------------------------------
// launcher
// ---------------------------------------------------------------------------
extern "C" void kernel_launch(void* const* d_in, const int* in_sizes, int n_in,
                              void* d_out, int out_size) {
    (void)in_sizes; (void)n_in; (void)out_size;
    const float* y   = (const float*)d_in[0];
    const float* sW0 = (const float*)d_in[1];
    const float* sb0 = (const float*)d_in[2];
    const float* sWh = (const float*)d_in[3];
    const float* sbh = (const float*)d_in[4];
    const float* sWo = (const float*)d_in[5];
    const float* sbo = (const float*)d_in[6];
    const float* tW0 = (const float*)d_in[7];
    const float* tb0 = (const float*)d_in[8];
    const float* tWh = (const float*)d_in[9];
    const float* tbh = (const float*)d_in[10];
    const float* tWo = (const float*)d_in[11];
    const float* tbo = (const float*)d_in[12];
    const float* lg  = (const float*)d_in[13];
    const float* bt  = (const float*)d_in[14];
    float* out = (float*)d_out;

    __nv_bfloat16 *h1h, *h1l, *h2h, *h2l, *y0h, *y0l, *whi, *wlo;
    float *yb, *sbuf, *tbuf;
    cudaGetSymbolAddress((void**)&h1h, g_h1h);
    cudaGetSymbolAddress((void**)&h1l, g_h1l);
    cudaGetSymbolAddress((void**)&h2h, g_h2h);
    cudaGetSymbolAddress((void**)&h2l, g_h2l);
    cudaGetSymbolAddress((void**)&y0h, g_y0h);
    cudaGetSymbolAddress((void**)&y0l, g_y0l);
    cudaGetSymbolAddress((void**)&whi, g_whi);
    cudaGetSymbolAddress((void**)&wlo, g_wlo);
    cudaGetSymbolAddress((void**)&yb, g_yb);
    cudaGetSymbolAddress((void**)&sbuf, g_sb);
    cudaGetSymbolAddress((void**)&tbuf, g_tb);

    const int SM_H = 3 * (2 * 128 * 80 + 2 * 128 * 80);  // 122880 (BN=128)
    const int SM_O = 3 * (2 * 128 * 80 + 2 * 32 * 80);   // 76800  (BN=32)
    cudaFuncSetAttribute(k_mma<128, 16, 1>, cudaFuncAttributeMaxDynamicSharedMemorySize, SM_H);
    cudaFuncSetAttribute(k_mma<128, 16, 2>, cudaFuncAttributeMaxDynamicSharedMemorySize, SM_H);
    cudaFuncSetAttribute(k_mma<128, 1, 1>,  cudaFuncAttributeMaxDynamicSharedMemorySize, SM_H);
    cudaFuncSetAttribute(k_mma<128, 1, 2>,  cudaFuncAttributeMaxDynamicSharedMemorySize, SM_H);
    cudaFuncSetAttribute(k_mma<32, 16, 0>,  cudaFuncAttributeMaxDynamicSharedMemorySize, SM_O);

    // weight prep
    { dim3 gh(1024, 1, 48); k_prep_h<<<gh, 256>>>(sWh, tWh); }
    { dim3 g0(64, 1, 16);   k_prep_l0<<<g0, 256>>>(sW0, tW0); }
    { dim3 go(64, 1, 16);   k_prep_out<<<go, 256>>>(sWo, tWo); }

    k_init<<<(BB + 255) / 256, 256>>>();
    k_prep_y0<<<(BB * dd) / 256, 256>>>(y);

    const dim3 GH(HH / 128, BB / 128);  // (4, 1024) hidden / layer0
    const dim3 GO(1, BB / 128);         // (1, 1024) out layers

    for (int b = 0; b < NBLK; ++b) {
        const float* ysrc = (b == 0) ? y : yb;
        const int sOff = (b & 1) ? dd : 0;
        if (b > 0) k_bnapply<<<(BB * DD + 255) / 256, 256>>>(sOff);

        const __nv_bfloat16* l0s_h = whi + HIDTOT_E + (size_t)(b * 2 + 0) * L0BLK_E;
        const __nv_bfloat16* l0s_l = wlo + HIDTOT_E + (size_t)(b * 2 + 0) * L0BLK_E;
        const __nv_bfloat16* l0t_h = whi + HIDTOT_E + (size_t)(b * 2 + 1) * L0BLK_E;
        const __nv_bfloat16* l0t_l = wlo + HIDTOT_E + (size_t)(b * 2 + 1) * L0BLK_E;
        const __nv_bfloat16* ots_h = whi + HIDTOT_E + L0TOT_E + (size_t)(b * 2 + 0) * OBLK_E;
        const __nv_bfloat16* ots_l = wlo + HIDTOT_E + L0TOT_E + (size_t)(b * 2 + 0) * OBLK_E;
        const __nv_bfloat16* ott_h = whi + HIDTOT_E + L0TOT_E + (size_t)(b * 2 + 1) * OBLK_E;
        const __nv_bfloat16* ott_l = wlo + HIDTOT_E + L0TOT_E + (size_t)(b * 2 + 1) * OBLK_E;

        // ---- s MLP (tanh) ----
        k_mma<128, 1, 1><<<GH, 256, SM_H>>>(y0h, y0l, l0s_h, l0s_l,
                                            sb0 + (size_t)b * HH, h1h, h1l, nullptr, HH);
        __nv_bfloat16 *ch = h1h, *cl = h1l, *nh = h2h, *nl = h2l;
        for (int l = 0; l < NLAYER; ++l) {
            const size_t ho = (size_t)(b * 6 + l) * HBLK_E;
            k_mma<128, 16, 1><<<GH, 256, SM_H>>>(ch, cl, whi + ho, wlo + ho,
                                                 sbh + (size_t)(b * 3 + l) * HH, nh, nl, nullptr, HH);
            __nv_bfloat16* t;
            t = ch; ch = nh; nh = t;
            t = cl; cl = nl; nl = t;
        }
        k_mma<32, 16, 0><<<GO, 256, SM_O>>>(ch, cl, ots_h, ots_l,
                                            sbo + (size_t)b * dd, nullptr, nullptr, sbuf, dd);

        // ---- t MLP (relu) ----
        k_mma<128, 1, 2><<<GH, 256, SM_H>>>(y0h, y0l, l0t_h, l0t_l,
                                            tb0 + (size_t)b * HH, h1h, h1l, nullptr, HH);
        ch = h1h; cl = h1l; nh = h2h; nl = h2l;
        for (int l = 0; l < NLAYER; ++l) {
            const size_t ho = (size_t)(b * 6 + 3 + l) * HBLK_E;
            k_mma<128, 16, 2><<<GH, 256, SM_H>>>(ch, cl, whi + ho, wlo + ho,
                                                 tbh + (size_t)(b * 3 + l) * HH, nh, nl, nullptr, HH);
            __nv_bfloat16* t;
            t = ch; ch = nh; nh = t;
            t = cl; cl = nl; nl = t;
        }
        k_mma<32, 16, 0><<<GO, 256, SM_O>>>(ch, cl, ott_h, ott_l,
                                            tbo + (size_t)b * dd, nullptr, nullptr, tbuf, dd);

        // ---- coupling + stats ----
        k_couple<<<(BB * 32 + 255) / 256, 256>>>(ysrc, sOff);
        k_colstats<<<128, dim3(64, 8)>>>();
        k_finalize<<<1, 64>>>(lg, bt, b);
    }

    k_output<<<(BB * DD + BB + 255) / 256, 256>>>(out);
}

// round 11
// speedup vs baseline: 3.0666x; 1.0904x over previous
#include <cuda_runtime.h>
#include <cuda_bf16.h>
#include <cstdint>
#include <math.h>

// Problem constants
#define BB 131072
#define DD 64
#define dd 32
#define HH 512
#define NLAYER 3
#define NBLK 8
#define EPS 1e-5f

// ---------------------------------------------------------------------------
// asm helpers (sm_80-era instructions only: valid at compute_103 target)
// ---------------------------------------------------------------------------
__device__ __forceinline__ uint32_t smem_u32(const void* p) {
    uint32_t a;
    asm("{ .reg .u64 t; cvta.to.shared.u64 t, %1; cvt.u32.u64 %0, t; }" : "=r"(a) : "l"(p));
    return a;
}
#define CP16(S, G) \
    asm volatile("cp.async.cg.shared.global [%0], [%1], 16;" :: "r"(S), "l"(G))
#define CP_COMMIT() asm volatile("cp.async.commit_group;" ::: "memory")
#define CP_WAIT0()  asm volatile("cp.async.wait_group 0;" ::: "memory")

#define LDSM4(R, ADDR) \
    asm volatile("ldmatrix.sync.aligned.m8n8.x4.shared.b16 {%0,%1,%2,%3}, [%4];" \
        : "=r"((R)[0]), "=r"((R)[1]), "=r"((R)[2]), "=r"((R)[3]) : "r"(ADDR))

#define MMA_BF16(D, A, B0, B1) \
    asm volatile("mma.sync.aligned.m16n8k16.row.col.f32.bf16.bf16.f32 " \
        "{%0,%1,%2,%3}, {%4,%5,%6,%7}, {%8,%9}, {%0,%1,%2,%3};" \
        : "+f"((D)[0]), "+f"((D)[1]), "+f"((D)[2]), "+f"((D)[3]) \
        : "r"((A)[0]), "r"((A)[1]), "r"((A)[2]), "r"((A)[3]), "r"(B0), "r"(B1))

// ---------------------------------------------------------------------------
// scratch (static device globals; no allocation)
// ---------------------------------------------------------------------------
__device__ __nv_bfloat16 g_h1h[(size_t)BB * HH];
__device__ __nv_bfloat16 g_h1l[(size_t)BB * HH];
__device__ __nv_bfloat16 g_h2h[(size_t)BB * HH];
__device__ __nv_bfloat16 g_h2l[(size_t)BB * HH];
__device__ __nv_bfloat16 g_y0h[(size_t)BB * dd];
__device__ __nv_bfloat16 g_y0l[(size_t)BB * dd];
__device__ float g_yb[(size_t)BB * DD];
__device__ float g_zb[(size_t)BB * DD];
__device__ float g_sb[(size_t)BB * dd];
__device__ float g_tb[(size_t)BB * dd];
__device__ float g_logdet[BB];
__device__ double g_csum[DD];
__device__ double g_csumsq[DD];
__device__ float g_scale[DD];
__device__ float g_shift[DD];
__device__ float g_scalar;

// weight blobs: [N][K] bf16, hi and lo splits
#define HBLK_E   262144UL
#define HIDTOT_E (48UL * HBLK_E)
#define L0BLK_E  16384UL
#define L0TOT_E  (16UL * L0BLK_E)
#define OBLK_E   16384UL
#define WTOT_E   (HIDTOT_E + L0TOT_E + 16UL * OBLK_E)
__device__ __nv_bfloat16 g_whi[WTOT_E];
__device__ __nv_bfloat16 g_wlo[WTOT_E];

// ---------------------------------------------------------------------------
// helpers
// ---------------------------------------------------------------------------
__device__ __forceinline__ void split1(float v, __nv_bfloat16& h, __nv_bfloat16& l) {
    h = __float2bfloat16(v);
    l = __float2bfloat16(v - __bfloat162float(h));
}
__device__ __forceinline__ uint32_t pack2(__nv_bfloat16 a, __nv_bfloat16 b) {
    return (uint32_t)__bfloat16_as_ushort(a) | ((uint32_t)__bfloat16_as_ushort(b) << 16);
}
__device__ __forceinline__ float fast_tanh(float x) {
    float e = __expf(2.0f * x);
    return 1.0f - __fdividef(2.0f, e + 1.0f);
}
__device__ __forceinline__ void split8pack(const float* f, uint4& hv, uint4& lv) {
    __nv_bfloat16 h[8], l[8];
#pragma unroll
    for (int j = 0; j < 8; ++j) split1(f[j], h[j], l[j]);
    hv.x = pack2(h[0], h[1]); hv.y = pack2(h[2], h[3]);
    hv.z = pack2(h[4], h[5]); hv.w = pack2(h[6], h[7]);
    lv.x = pack2(l[0], l[1]); lv.y = pack2(l[2], l[3]);
    lv.z = pack2(l[4], l[5]); lv.w = pack2(l[6], l[7]);
}

// ---------------------------------------------------------------------------
// weight prep: W[K][N] fp32 -> blob[n*K + k] bf16 hi/lo (coalesced reads)
// thread t: n = t % Ndim (consecutive), k0 = (t / Ndim)*8
// ---------------------------------------------------------------------------
__device__ __forceinline__ void prep8(const float* W, int Kdim, int Ndim,
                                      __nv_bfloat16* dh, __nv_bfloat16* dl, int t) {
    int n = t % Ndim;
    int k0 = (t / Ndim) * 8;
    float f[8];
#pragma unroll
    for (int j = 0; j < 8; ++j) f[j] = W[(size_t)(k0 + j) * Ndim + n];
    uint4 hv, lv;
    split8pack(f, hv, lv);
    size_t o = (size_t)n * Kdim + k0;
    *(uint4*)(dh + o) = hv;
    *(uint4*)(dl + o) = lv;
}

__global__ void k_prep_h(const float* __restrict__ sWh, const float* __restrict__ tWh) {
    int z = blockIdx.z, b = z / 6, r = z % 6;
    const float* W = (r < 3) ? sWh + (size_t)(b * 3 + r) * HH * HH
                             : tWh + (size_t)(b * 3 + (r - 3)) * HH * HH;
    int t = blockIdx.x * 256 + threadIdx.x;  // 32768 per matrix
    prep8(W, HH, HH, g_whi + (size_t)z * HBLK_E, g_wlo + (size_t)z * HBLK_E, t);
}
__global__ void k_prep_l0(const float* __restrict__ sW0, const float* __restrict__ tW0) {
    int z = blockIdx.z, b = z >> 1, m = z & 1;
    const float* W = (m ? tW0 : sW0) + (size_t)b * dd * HH;   // [32][512]
    int t = blockIdx.x * 256 + threadIdx.x;                   // 2048 per matrix
    prep8(W, dd, HH, g_whi + HIDTOT_E + (size_t)z * L0BLK_E,
          g_wlo + HIDTOT_E + (size_t)z * L0BLK_E, t);
}
__global__ void k_prep_out(const float* __restrict__ sWo, const float* __restrict__ tWo) {
    int z = blockIdx.z, b = z >> 1, m = z & 1;
    const float* W = (m ? tWo : sWo) + (size_t)b * HH * dd;   // [512][32]
    int t = blockIdx.x * 256 + threadIdx.x;                   // 2048 per matrix
    prep8(W, HH, dd, g_whi + HIDTOT_E + L0TOT_E + (size_t)z * OBLK_E,
          g_wlo + HIDTOT_E + L0TOT_E + (size_t)z * OBLK_E, t);
}
__global__ void k_prep_y0(const float* __restrict__ y) {
    int idx = blockIdx.x * 256 + threadIdx.x;   // BB*32
    int r = idx >> 5, c = idx & 31;
    float v = y[(size_t)r * DD + c];            // sOff = 0 for block 0
    __nv_bfloat16 h, l; split1(v, h, l);
    g_y0h[idx] = h; g_y0l[idx] = l;
}

// ---------------------------------------------------------------------------
// HMMA GEMM: C[M,N] = act(A[M,K] @ W[K,N] + bias), bf16 hi/lo x3
// grid = (N/BN, M/128), block = 128 (4 warps), 2-stage cp.async, 2 CTAs/SM.
// BN=128: warp grid 2x2, warp tile 64x64. BN=32: warp grid 4x1, tile 32x32.
// ---------------------------------------------------------------------------
template <int BN, int NK, int ACT>
__global__ void __launch_bounds__(128, 2) k_mma(
    const __nv_bfloat16* __restrict__ Ahi, const __nv_bfloat16* __restrict__ Alo,
    const __nv_bfloat16* __restrict__ Bhi, const __nv_bfloat16* __restrict__ Blo,
    const float* __restrict__ bias,
    __nv_bfloat16* __restrict__ Chi, __nv_bfloat16* __restrict__ Clo,
    float* __restrict__ Cf, int ldc)
{
    constexpr int K  = NK * 32;
    constexpr int MT = (BN == 128) ? 4 : 2;
    constexpr int NT = (BN == 128) ? 8 : 4;
    constexpr uint32_t AST = 128 * 80;      // one A half per stage
    constexpr uint32_t BST = BN * 80;
    constexpr uint32_t SS  = 2 * AST + 2 * BST;
    constexpr int T_TOT = 1024 + BN * 8;

    extern __shared__ unsigned char smraw[];
    const uint32_t sb = smem_u32(smraw);
    const int tid = threadIdx.x;
    const int wid = tid >> 5;
    const int L = tid & 31;
    const size_t bm = (size_t)blockIdx.y * 128;
    const int bn = blockIdx.x * BN;
    const int wm = (BN == 128) ? (wid >> 1) * 64 : wid * 32;
    const int wn = (BN == 128) ? (wid & 1) * 64 : 0;

    float acc[MT][NT][4];
#pragma unroll
    for (int i = 0; i < MT; ++i)
#pragma unroll
        for (int j = 0; j < NT; ++j)
#pragma unroll
            for (int q = 0; q < 4; ++q) acc[i][j][q] = 0.0f;

    const uint32_t a_off = (uint32_t)(wm + (L & 15)) * 80u + (uint32_t)((L >> 4) << 4);
    const uint32_t b_off = (uint32_t)(wn + (L & 7)) * 80u + (uint32_t)((L >> 3) << 4);

    auto load_stage = [&](int st, int kc) {
        const uint32_t s0 = sb + (uint32_t)st * SS;
        const size_t akb = (size_t)kc * 32;
#pragma unroll
        for (int q = tid; q < T_TOT; q += 128) {
            if (q < 512) {
                int r = q >> 2, c = q & 3;
                CP16(s0 + (uint32_t)r * 80u + (uint32_t)c * 16u,
                     Ahi + (bm + r) * K + akb + c * 8);
            } else if (q < 1024) {
                int p = q - 512; int r = p >> 2, c = p & 3;
                CP16(s0 + AST + (uint32_t)r * 80u + (uint32_t)c * 16u,
                     Alo + (bm + r) * K + akb + c * 8);
            } else if (q < 1024 + BN * 4) {
                int p = q - 1024; int r = p >> 2, c = p & 3;
                CP16(s0 + 2 * AST + (uint32_t)r * 80u + (uint32_t)c * 16u,
                     Bhi + (size_t)(bn + r) * K + akb + c * 8);
            } else {
                int p = q - 1024 - BN * 4; int r = p >> 2, c = p & 3;
                CP16(s0 + 2 * AST + BST + (uint32_t)r * 80u + (uint32_t)c * 16u,
                     Blo + (size_t)(bn + r) * K + akb + c * 8);
            }
        }
    };

    load_stage(0, 0);
    CP_COMMIT();

    for (int kc = 0; kc < NK; ++kc) {
        CP_WAIT0();            // stage kc complete (only pending group)
        __syncthreads();       // all warps done reading buffer (kc+1)&1
        if (kc + 1 < NK) load_stage((kc + 1) & 1, kc + 1);
        CP_COMMIT();
        const uint32_t s0 = sb + (uint32_t)(kc & 1) * SS;

        uint32_t Bh[NT][4], Bl[NT][4];
#pragma unroll
        for (int j = 0; j < NT; ++j) LDSM4(Bh[j], s0 + 2 * AST + b_off + j * 640u);
#pragma unroll
        for (int j = 0; j < NT; ++j) LDSM4(Bl[j], s0 + 2 * AST + BST + b_off + j * 640u);

#pragma unroll
        for (int ks = 0; ks < 2; ++ks) {
            uint32_t Ah[MT][4], Al[MT][4];
#pragma unroll
            for (int i = 0; i < MT; ++i) LDSM4(Ah[i], s0 + a_off + i * 1280u + ks * 32u);
#pragma unroll
            for (int i = 0; i < MT; ++i) LDSM4(Al[i], s0 + AST + a_off + i * 1280u + ks * 32u);
            // product-outer ordering: same-acc MMAs are MT*NT apart (no RAW chains)
#pragma unroll
            for (int i = 0; i < MT; ++i)
#pragma unroll
                for (int j = 0; j < NT; ++j)
                    MMA_BF16(acc[i][j], Ah[i], Bh[j][2 * ks], Bh[j][2 * ks + 1]);
#pragma unroll
            for (int i = 0; i < MT; ++i)
#pragma unroll
                for (int j = 0; j < NT; ++j)
                    MMA_BF16(acc[i][j], Al[i], Bh[j][2 * ks], Bh[j][2 * ks + 1]);
#pragma unroll
            for (int i = 0; i < MT; ++i)
#pragma unroll
                for (int j = 0; j < NT; ++j)
                    MMA_BF16(acc[i][j], Ah[i], Bl[j][2 * ks], Bl[j][2 * ks + 1]);
        }
    }

    // epilogue
#pragma unroll
    for (int i = 0; i < MT; ++i) {
        const size_t r0 = bm + wm + i * 16 + (L >> 2);
        const size_t r1 = r0 + 8;
#pragma unroll
        for (int j = 0; j < NT; ++j) {
            const int n = bn + wn + j * 8 + ((L & 3) << 1);
            const float2 bs = *(const float2*)(bias + n);
            float v0 = acc[i][j][0] + bs.x;
            float v1 = acc[i][j][1] + bs.y;
            float v2 = acc[i][j][2] + bs.x;
            float v3 = acc[i][j][3] + bs.y;
            if (ACT == 1) {
                v0 = fast_tanh(v0); v1 = fast_tanh(v1);
                v2 = fast_tanh(v2); v3 = fast_tanh(v3);
            } else if (ACT == 2) {
                v0 = fmaxf(v0, 0.f); v1 = fmaxf(v1, 0.f);
                v2 = fmaxf(v2, 0.f); v3 = fmaxf(v3, 0.f);
            }
            if (ACT == 0) {
                *(float2*)(Cf + r0 * ldc + n) = make_float2(v0, v1);
                *(float2*)(Cf + r1 * ldc + n) = make_float2(v2, v3);
            } else {
                __nv_bfloat16 h0, l0, h1, l1, h2, l2, h3, l3;
                split1(v0, h0, l0); split1(v1, h1, l1);
                split1(v2, h2, l2); split1(v3, h3, l3);
                *(uint32_t*)(Chi + r0 * ldc + n) = pack2(h0, h1);
                *(uint32_t*)(Clo + r0 * ldc + n) = pack2(l0, l1);
                *(uint32_t*)(Chi + r1 * ldc + n) = pack2(h2, h3);
                *(uint32_t*)(Clo + r1 * ldc + n) = pack2(l2, l3);
            }
        }
    }
}

// ---------------------------------------------------------------------------
// small kernels
// ---------------------------------------------------------------------------
__global__ void k_init() {
    int idx = blockIdx.x * blockDim.x + threadIdx.x;
    if (idx < BB) g_logdet[idx] = 0.0f;
    if (idx < DD) { g_csum[idx] = 0.0; g_csumsq[idx] = 0.0; }
    if (idx == 0) g_scalar = 0.0f;
}
__global__ void k_bnapply(int sOff) {
    int idx = blockIdx.x * blockDim.x + threadIdx.x;
    if (idx < BB * DD) {
        int c = idx & (DD - 1);
        int r = idx >> 6;
        float v = g_zb[idx] * g_scale[c] + g_shift[c];
        g_yb[idx] = v;
        int cc = c - sOff;
        if (cc >= 0 && cc < dd) {
            __nv_bfloat16 h, l; split1(v, h, l);
            size_t o = (size_t)r * dd + cc;
            g_y0h[o] = h; g_y0l[o] = l;
        }
    }
}
__global__ void k_couple(const float* __restrict__ ysrc, int sOff) {
    int gt = blockIdx.x * blockDim.x + threadIdx.x;
    int row = gt >> 5;
    int j = gt & 31;
    if (row >= BB) return;
    int cOff = dd - sOff;
    float sv = g_sb[(size_t)row * dd + j];
    float tv = g_tb[(size_t)row * dd + j];
    float ys = ysrc[(size_t)row * DD + sOff + j];
    float yc = ysrc[(size_t)row * DD + cOff + j];
    float zc = yc * expf(sv) + tv;
    g_zb[(size_t)row * DD + sOff + j] = ys;
    g_zb[(size_t)row * DD + cOff + j] = zc;
    float sum = sv;
#pragma unroll
    for (int o = 16; o > 0; o >>= 1) sum += __shfl_xor_sync(0xffffffffu, sum, o);
    if (j == 0) g_logdet[row] += sum;
}
__global__ void k_colstats() {
    int c = threadIdx.x;
    int r = threadIdx.y;
    int start = blockIdx.x * 1024;
    float s = 0.0f, q = 0.0f;
    for (int i = start + r; i < start + 1024; i += 8) {
        float v = g_zb[(size_t)i * DD + c];
        s += v; q += v * v;
    }
    __shared__ float shs[8][64];
    __shared__ float shq[8][64];
    shs[r][c] = s; shq[r][c] = q;
    __syncthreads();
    if (r == 0) {
        double S = 0.0, Q = 0.0;
#pragma unroll
        for (int k = 0; k < 8; ++k) { S += (double)shs[k][c]; Q += (double)shq[k][c]; }
        atomicAdd(&g_csum[c], S);
        atomicAdd(&g_csumsq[c], Q);
    }
}
__global__ void k_finalize(const float* __restrict__ lg, const float* __restrict__ bt, int b) {
    int c = threadIdx.x;
    double mean = g_csum[c] / (double)BB;
    double var = (g_csumsq[c] - (double)BB * mean * mean) / (double)(BB - 1);
    double vpe = var + (double)EPS;
    float invstd = (float)(1.0 / sqrt(vpe));
    float lgc = lg[b * DD + c];
    float sc = expf(lgc) * invstd;
    g_scale[c] = sc;
    g_shift[c] = bt[b * DD + c] - (float)mean * sc;
    float term = lgc - 0.5f * (float)log(vpe);
    g_csum[c] = 0.0;
    g_csumsq[c] = 0.0;
    __shared__ float red[64];
    red[c] = term;
    __syncthreads();
    for (int o = 32; o > 0; o >>= 1) {
        if (c < o) red[c] += red[c + o];
        __syncthreads();
    }
    if (c == 0) g_scalar += red[0];
}
__global__ void k_output(float* __restrict__ out) {
    int idx = blockIdx.x * blockDim.x + threadIdx.x;
    if (idx < BB * DD) {
        int c = idx & (DD - 1);
        out[idx] = g_zb[idx] * g_scale[c] + g_shift[c];
    } else if (idx < BB * DD + BB) {
        int i = idx - BB * DD;
        out[(size_t)BB * DD + i] = g_logdet[i] + g_scalar;
    }
}

// ---------------------------------------------------------------------------
// launcher
// ---------------------------------------------------------------------------
extern "C" void kernel_launch(void* const* d_in, const int* in_sizes, int n_in,
                              void* d_out, int out_size) {
    (void)in_sizes; (void)n_in; (void)out_size;
    const float* y   = (const float*)d_in[0];
    const float* sW0 = (const float*)d_in[1];
    const float* sb0 = (const float*)d_in[2];
    const float* sWh = (const float*)d_in[3];
    const float* sbh = (const float*)d_in[4];
    const float* sWo = (const float*)d_in[5];
    const float* sbo = (const float*)d_in[6];
    const float* tW0 = (const float*)d_in[7];
    const float* tb0 = (const float*)d_in[8];
    const float* tWh = (const float*)d_in[9];
    const float* tbh = (const float*)d_in[10];
    const float* tWo = (const float*)d_in[11];
    const float* tbo = (const float*)d_in[12];
    const float* lg  = (const float*)d_in[13];
    const float* bt  = (const float*)d_in[14];
    float* out = (float*)d_out;

    __nv_bfloat16 *h1h, *h1l, *h2h, *h2l, *y0h, *y0l, *whi, *wlo;
    float *yb, *sbuf, *tbuf;
    cudaGetSymbolAddress((void**)&h1h, g_h1h);
    cudaGetSymbolAddress((void**)&h1l, g_h1l);
    cudaGetSymbolAddress((void**)&h2h, g_h2h);
    cudaGetSymbolAddress((void**)&h2l, g_h2l);
    cudaGetSymbolAddress((void**)&y0h, g_y0h);
    cudaGetSymbolAddress((void**)&y0l, g_y0l);
    cudaGetSymbolAddress((void**)&whi, g_whi);
    cudaGetSymbolAddress((void**)&wlo, g_wlo);
    cudaGetSymbolAddress((void**)&yb, g_yb);
    cudaGetSymbolAddress((void**)&sbuf, g_sb);
    cudaGetSymbolAddress((void**)&tbuf, g_tb);

    const int SM_H = 2 * (2 * 128 * 80 + 2 * 128 * 80);  // 81920 (BN=128)
    const int SM_O = 2 * (2 * 128 * 80 + 2 * 32 * 80);   // 51200 (BN=32)
    cudaFuncSetAttribute(k_mma<128, 16, 1>, cudaFuncAttributeMaxDynamicSharedMemorySize, SM_H);
    cudaFuncSetAttribute(k_mma<128, 16, 2>, cudaFuncAttributeMaxDynamicSharedMemorySize, SM_H);
    cudaFuncSetAttribute(k_mma<128, 1, 1>,  cudaFuncAttributeMaxDynamicSharedMemorySize, SM_H);
    cudaFuncSetAttribute(k_mma<128, 1, 2>,  cudaFuncAttributeMaxDynamicSharedMemorySize, SM_H);
    cudaFuncSetAttribute(k_mma<32, 16, 0>,  cudaFuncAttributeMaxDynamicSharedMemorySize, SM_O);

    // weight prep
    { dim3 gh(128, 1, 48); k_prep_h<<<gh, 256>>>(sWh, tWh); }
    { dim3 g0(8, 1, 16);   k_prep_l0<<<g0, 256>>>(sW0, tW0); }
    { dim3 go(8, 1, 16);   k_prep_out<<<go, 256>>>(sWo, tWo); }

    k_init<<<(BB + 255) / 256, 256>>>();
    k_prep_y0<<<(BB * dd) / 256, 256>>>(y);

    const dim3 GH(HH / 128, BB / 128);  // (4, 1024)
    const dim3 GO(1, BB / 128);         // (1, 1024)

    for (int b = 0; b < NBLK; ++b) {
        const float* ysrc = (b == 0) ? y : yb;
        const int sOff = (b & 1) ? dd : 0;
        if (b > 0) k_bnapply<<<(BB * DD + 255) / 256, 256>>>(sOff);

        const __nv_bfloat16* l0s_h = whi + HIDTOT_E + (size_t)(b * 2 + 0) * L0BLK_E;
        const __nv_bfloat16* l0s_l = wlo + HIDTOT_E + (size_t)(b * 2 + 0) * L0BLK_E;
        const __nv_bfloat16* l0t_h = whi + HIDTOT_E + (size_t)(b * 2 + 1) * L0BLK_E;
        const __nv_bfloat16* l0t_l = wlo + HIDTOT_E + (size_t)(b * 2 + 1) * L0BLK_E;
        const __nv_bfloat16* ots_h = whi + HIDTOT_E + L0TOT_E + (size_t)(b * 2 + 0) * OBLK_E;
        const __nv_bfloat16* ots_l = wlo + HIDTOT_E + L0TOT_E + (size_t)(b * 2 + 0) * OBLK_E;
        const __nv_bfloat16* ott_h = whi + HIDTOT_E + L0TOT_E + (size_t)(b * 2 + 1) * OBLK_E;
        const __nv_bfloat16* ott_l = wlo + HIDTOT_E + L0TOT_E + (size_t)(b * 2 + 1) * OBLK_E;

        // ---- s MLP (tanh) ----
        k_mma<128, 1, 1><<<GH, 128, SM_H>>>(y0h, y0l, l0s_h, l0s_l,
                                            sb0 + (size_t)b * HH, h1h, h1l, nullptr, HH);
        __nv_bfloat16 *ch = h1h, *cl = h1l, *nh = h2h, *nl = h2l;
        for (int l = 0; l < NLAYER; ++l) {
            const size_t ho = (size_t)(b * 6 + l) * HBLK_E;
            k_mma<128, 16, 1><<<GH, 128, SM_H>>>(ch, cl, whi + ho, wlo + ho,
                                                 sbh + (size_t)(b * 3 + l) * HH, nh, nl, nullptr, HH);
            __nv_bfloat16* t;
            t = ch; ch = nh; nh = t;
            t = cl; cl = nl; nl = t;
        }
        k_mma<32, 16, 0><<<GO, 128, SM_O>>>(ch, cl, ots_h, ots_l,
                                            sbo + (size_t)b * dd, nullptr, nullptr, sbuf, dd);

        // ---- t MLP (relu) ----
        k_mma<128, 1, 2><<<GH, 128, SM_H>>>(y0h, y0l, l0t_h, l0t_l,
                                            tb0 + (size_t)b * HH, h1h, h1l, nullptr, HH);
        ch = h1h; cl = h1l; nh = h2h; nl = h2l;
        for (int l = 0; l < NLAYER; ++l) {
            const size_t ho = (size_t)(b * 6 + 3 + l) * HBLK_E;
            k_mma<128, 16, 2><<<GH, 128, SM_H>>>(ch, cl, whi + ho, wlo + ho,
                                                 tbh + (size_t)(b * 3 + l) * HH, nh, nl, nullptr, HH);
            __nv_bfloat16* t;
            t = ch; ch = nh; nh = t;
            t = cl; cl = nl; nl = t;
        }
        k_mma<32, 16, 0><<<GO, 128, SM_O>>>(ch, cl, ott_h, ott_l,
                                            tbo + (size_t)b * dd, nullptr, nullptr, tbuf, dd);

        // ---- coupling + stats ----
        k_couple<<<(BB * 32 + 255) / 256, 256>>>(ysrc, sOff);
        k_colstats<<<128, dim3(64, 8)>>>();
        k_finalize<<<1, 64>>>(lg, bt, b);
    }

    k_output<<<(BB * DD + BB + 255) / 256, 256>>>(out);
}